// round 9
// baseline (speedup 1.0000x reference)
#include <cuda_runtime.h>
#include <cuda_fp16.h>
#include <cstdint>

#define Hd   1024
#define Bb   16
#define Ss   512
#define Kk   32
#define Ee   1024
#define NCAT 3072

// ---------------- scratch ----------------------------------------------------
__device__ __half g_Xh[512*Hd];         // full_nodes fp16  [512][1024]
__device__ __half g_Wh[NCAT*Hd];        // Wcat^T fp16      [3072 n][1024 k]
__device__ float g_node_hidden[512*Hd];
__device__ float g_Aj[512*Hd];          // edge bias folded in
__device__ float g_Ai[512*Hd];
__device__ float g_cls_hidden[Bb*Hd];
__device__ float g_invconst[2];         // invalid-edge logits
__device__ int   g_n[Bb];

// ---------------- helpers ----------------------------------------------------
__device__ __forceinline__ float tanh_fast(float x) {
    float e = __expf(2.0f * x);
    return 1.0f - __fdividef(2.0f, e + 1.0f);
}

__device__ __forceinline__ uint32_t smem_u32(const void* p) {
    uint32_t a;
    asm("{ .reg .u64 t; cvta.to.shared.u64 t, %1; cvt.u32.u64 %0, t; }" : "=r"(a) : "l"(p));
    return a;
}

__device__ __forceinline__ void cp16(uint32_t saddr, const void* g) {
    asm volatile("cp.async.cg.shared.global [%0], [%1], 16;" :: "r"(saddr), "l"(g));
}
__device__ __forceinline__ void cp_commit() {
    asm volatile("cp.async.commit_group;");
}
template <int N>
__device__ __forceinline__ void cp_wait() {
    asm volatile("cp.async.wait_group %0;" :: "n"(N));
}

__device__ __forceinline__ void ldsm_x4(uint32_t& r0, uint32_t& r1, uint32_t& r2,
                                        uint32_t& r3, uint32_t addr) {
    asm volatile("ldmatrix.sync.aligned.m8n8.x4.shared.b16 {%0,%1,%2,%3}, [%4];"
                 : "=r"(r0), "=r"(r1), "=r"(r2), "=r"(r3) : "r"(addr));
}
__device__ __forceinline__ void ldsm_x2(uint32_t& r0, uint32_t& r1, uint32_t addr) {
    asm volatile("ldmatrix.sync.aligned.m8n8.x2.shared.b16 {%0,%1}, [%2];"
                 : "=r"(r0), "=r"(r1) : "r"(addr));
}
__device__ __forceinline__ void mma16816h(float* d, const uint32_t* a, const uint32_t* b) {
    asm volatile(
        "mma.sync.aligned.m16n8k16.row.col.f32.f16.f16.f32 "
        "{%0,%1,%2,%3}, {%4,%5,%6,%7}, {%8,%9}, {%0,%1,%2,%3};"
        : "+f"(d[0]), "+f"(d[1]), "+f"(d[2]), "+f"(d[3])
        : "r"(a[0]), "r"(a[1]), "r"(a[2]), "r"(a[3]), "r"(b[0]), "r"(b[1]));
}

__device__ __forceinline__ void block_reduce2(float& a0, float& a1, float* red) {
    #pragma unroll
    for (int o = 16; o > 0; o >>= 1) {
        a0 += __shfl_down_sync(0xffffffffu, a0, o);
        a1 += __shfl_down_sync(0xffffffffu, a1, o);
    }
    int w = threadIdx.x >> 5;
    if ((threadIdx.x & 31) == 0) { red[2*w] = a0; red[2*w+1] = a1; }
    __syncthreads();
    if (threadIdx.x == 0) {
        a0 = red[0]; a1 = red[1];
        for (int w2 = 1; w2 < (int)(blockDim.x >> 5); w2++) {
            a0 += red[2*w2]; a1 += red[2*w2+1];
        }
    }
}

// ======== 1. k_prep: meta | wsplit | invconst | cls2, flat grid =============
// blocks: [0,512) meta; [512,3584) wsplit; 3584 invconst; [3585,3617) cls2
__global__ __launch_bounds__(256) void k_prep(const float* __restrict__ seq,
                                              const int* __restrict__ P,
                                              const float* __restrict__ nodeW,
                                              const float* __restrict__ eW,
                                              const float* __restrict__ eb,
                                              const float* __restrict__ eoW,
                                              const float* __restrict__ eob,
                                              const float* __restrict__ nafW,
                                              const float* __restrict__ nafb,
                                              const float* __restrict__ clsW,
                                              const float* __restrict__ clsb) {
    __shared__ __align__(16) char shm[49152];
    int blk = blockIdx.x;
    int t   = threadIdx.x;

    if (blk < 512) {
        // ---- meta: segment mean for (b, k); skip row k==n (cls2 writes it) ----
        int k = blk & 31, b = blk >> 5;
        int n = 0;
        #pragma unroll
        for (int j = 0; j < Kk - 1; j++) n += (P[b*Kk + 1 + j] > 0);
        if (k == 0 && t == 0) g_n[b] = n;
        long row = (long)(b*Kk + k) * Hd;
        if (k < n) {
            int end   = P[b*Kk + 1 + k];
            int start = (k == 0) ? 1 : (P[b*Kk + k] + 1);
            float inv = 1.0f / (float)(end - start + 1);
            #pragma unroll
            for (int u = 0; u < Hd/256; u++) {
                int h = t + u*256;
                float s = 0.0f;
                for (int p = start; p <= end; p++)
                    s += seq[((long)b*Ss + p)*Hd + h];
                g_Xh[row + h] = __float2half(s * inv);
            }
        } else if (k > n) {
            #pragma unroll
            for (int u = 0; u < Hd/256; u++)
                g_Xh[row + t + u*256] = __float2half(0.f);
        }
        return;
    }

    if (blk < 3584) {
        // ---- wsplit: transpose + algebra into fp16 Wh[n][k] ----
        float (*tile)[33] = (float(*)[33])shm;
        int tb = blk - 512;
        int tx = t & 31, ty = t >> 5;
        int c0 = (tb % 96) * 32, k0 = (tb / 96) * 32;
        #pragma unroll
        for (int r = 0; r < 4; r++) {
            int kk = k0 + ty + r*8;
            int c  = c0 + tx;
            float v;
            if (c < Hd) {
                v = nodeW[kk*Hd + c];
            } else if (c < 2*Hd) {
                int h = c - Hd;
                v = eW[kk*Hd + h] + eW[(2*Hd + kk)*Hd + h];
            } else {
                int h = c - 2*Hd;
                v = eW[(Hd + kk)*Hd + h] - eW[(2*Hd + kk)*Hd + h];
            }
            tile[ty + r*8][tx] = v;
        }
        __syncthreads();
        #pragma unroll
        for (int r = 0; r < 4; r++) {
            int cl = ty + r*8;
            g_Wh[(long)(c0 + cl)*Hd + k0 + tx] = __float2half(tile[tx][cl]);
        }
        return;
    }

    if (blk == 3584) {
        // ---- invalid-edge constant ----
        float* red = (float*)shm;
        float a0 = 0.f, a1 = 0.f;
        #pragma unroll
        for (int u = 0; u < Hd/256; u++) {
            int h = t + u*256;
            float v = tanh_fast(eb[h]);
            a0 = fmaf(v, eoW[2*h  ], a0);
            a1 = fmaf(v, eoW[2*h+1], a1);
        }
        block_reduce2(a0, a1, red);
        if (t == 0) { g_invconst[0] = a0 + eob[0]; g_invconst[1] = a1 + eob[1]; }
        return;
    }

    // ---- cls2: batched GEMVs, 256 thr = two 32-col halves, 64 cols/block ----
    {
        float (*xs)[64][16] = (float(*)[64][16])shm;           // 16 KB
        float (*red)[4][32][16] = (float(*)[4][32][16])(shm + 16384); // 32 KB
        int idx = blk - 3585;
        int m = idx >> 4, colblk = idx & 15;
        const float* W    = m ? clsW : nafW;
        const float* bias = m ? clsb : nafb;
        int half = t >> 7, t1 = t & 127;
        int lane = t1 & 31, ks = t1 >> 5;
        int colg = colblk*64 + half*32 + lane;

        float acc[16];
        #pragma unroll
        for (int b = 0; b < 16; b++) acc[b] = 0.0f;

        for (int tt = 0; tt < 4; tt++) {
            __syncthreads();
            #pragma unroll
            for (int io = 0; io < 16; io++) {
                int flat = io*256 + t;
                int b    = flat >> 8;
                int rem  = flat & 255;
                int ks2  = rem >> 6;
                int kk   = rem & 63;
                xs[ks2][kk][b] = seq[(long)b*Ss*Hd + ks2*256 + tt*64 + kk];
            }
            __syncthreads();
            #pragma unroll 8
            for (int kk = 0; kk < 64; kk++) {
                float w = W[(ks*256 + tt*64 + kk)*Hd + colg];
                #pragma unroll
                for (int b2 = 0; b2 < 8; b2++) {
                    float2 x2 = *(const float2*)&xs[ks][kk][b2*2];
                    acc[2*b2]   = fmaf(x2.x, w, acc[2*b2]);
                    acc[2*b2+1] = fmaf(x2.y, w, acc[2*b2+1]);
                }
            }
        }
        #pragma unroll
        for (int b = 0; b < 16; b++) red[half][ks][lane][b] = acc[b];
        __syncthreads();
        // alias n-table onto the (now dead) xs area
        int* sn = (int*)shm;
        if (t < 16) {
            int n = 0;
            #pragma unroll
            for (int j = 0; j < Kk - 1; j++) n += (P[t*Kk + 1 + j] > 0);
            sn[t] = n;
        }
        __syncthreads();
        #pragma unroll
        for (int q = 0; q < 4; q++) {
            int o = q*128 + t1;
            int c = o & 31;
            int b = (o >> 5) & 15;
            float v = red[half][0][c][b] + red[half][1][c][b]
                    + red[half][2][c][b] + red[half][3][c][b];
            int cg = colblk*64 + half*32 + c;
            v += bias[cg];
            if (m == 0) {
                g_Xh[(long)(b*Kk + sn[b])*Hd + cg] = __float2half(v);
            } else {
                g_cls_hidden[b*Hd + cg] = tanh_fast(v);
            }
        }
    }
}

// ======== 2. fp16 tensor GEMM, 4-stage cp.async =============================
// C(512x3072) = X @ Wcat. Tile M=64, N=128, k-chunk 32, 128 thr, grid (24,8).
#define ROWB 80
#define A_OFF 0
#define B_OFF (64*ROWB)
#define STAGE_B ((64+128)*ROWB)    // 15360 B
__global__ __launch_bounds__(128) void k_gemm(const float* __restrict__ node_b,
                                              const float* __restrict__ edge_b) {
    extern __shared__ __align__(16) char sm[];   // 4 * STAGE_B

    int tid  = threadIdx.x;
    int wid  = tid >> 5, lane = tid & 31;
    int wm   = wid & 1;
    int wn   = wid >> 1;
    int bn   = blockIdx.x, bm = blockIdx.y;

    const char* gX = (const char*)g_Xh + (long)bm*64*2048;
    const char* gW = (const char*)g_Wh + (long)bn*128*2048;

    uint32_t smb = smem_u32(sm);

    auto load_stage = [&](int ch, int st) {
        long gk = (long)ch * 64;
        uint32_t sb = smb + st*STAGE_B;
        #pragma unroll
        for (int i = 0; i < 6; i++) {
            int idx = tid + i*128;
            if (idx < 256) {
                int r = idx >> 2, c = (idx & 3)*16;
                cp16(sb + A_OFF + r*ROWB + c, gX + (long)r*2048 + gk + c);
            } else {
                int j = idx - 256;
                int r = j >> 2, c = (j & 3)*16;
                cp16(sb + B_OFF + r*ROWB + c, gW + (long)r*2048 + gk + c);
            }
        }
    };

    float acc[2][8][4];
    #pragma unroll
    for (int mt = 0; mt < 2; mt++)
        #pragma unroll
        for (int nt = 0; nt < 8; nt++)
            #pragma unroll
            for (int q = 0; q < 4; q++) acc[mt][nt][q] = 0.0f;

    int a_row  = wm*32 + (lane & 15);
    int a_koff = (lane >> 4) * 16;
    int b_row  = wn*64 + (lane & 7);
    int b_koff = ((lane >> 3) & 1) * 16;

    load_stage(0, 0); cp_commit();
    load_stage(1, 1); cp_commit();
    load_stage(2, 2); cp_commit();

    for (int ch = 0; ch < 32; ch++) {
        cp_wait<2>();
        __syncthreads();               // single barrier per chunk
        uint32_t sbase = smb + (ch & 3)*STAGE_B;

        #pragma unroll
        for (int ks = 0; ks < 2; ks++) {
            uint32_t a[2][4];
            #pragma unroll
            for (int mt = 0; mt < 2; mt++) {
                uint32_t ao = (uint32_t)((a_row + mt*16)*ROWB + ks*32 + a_koff);
                ldsm_x4(a[mt][0], a[mt][1], a[mt][2], a[mt][3], sbase + A_OFF + ao);
            }
            #pragma unroll
            for (int nt = 0; nt < 8; nt++) {
                uint32_t bo = (uint32_t)((b_row + nt*8)*ROWB + ks*32 + b_koff);
                uint32_t bf[2];
                ldsm_x2(bf[0], bf[1], sbase + B_OFF + bo);
                #pragma unroll
                for (int mt = 0; mt < 2; mt++)
                    mma16816h(acc[mt][nt], a[mt], bf);
            }
        }
        if (ch + 3 < 32) load_stage(ch + 3, (ch + 3) & 3);
        cp_commit();
    }

    // ---- epilogue ----
    int g = lane >> 2, t = lane & 3;
    int region = bn >> 3;
    #pragma unroll
    for (int mt = 0; mt < 2; mt++) {
        #pragma unroll
        for (int nt = 0; nt < 8; nt++) {
            int col = bn*128 + wn*64 + nt*8 + t*2;
            #pragma unroll
            for (int half = 0; half < 2; half++) {
                int row = bm*64 + wm*32 + mt*16 + g + half*8;
                float v0 = acc[mt][nt][half*2 + 0];
                float v1 = acc[mt][nt][half*2 + 1];
                if (region == 0) {
                    float2 o = make_float2(tanh_fast(v0 + node_b[col]),
                                           tanh_fast(v1 + node_b[col+1]));
                    *(float2*)&g_node_hidden[(long)row*Hd + col] = o;
                } else if (region == 1) {
                    int h = col - Hd;
                    float2 o = make_float2(v0 + edge_b[h], v1 + edge_b[h+1]);
                    *(float2*)&g_Aj[(long)row*Hd + h] = o;
                } else {
                    int h = col - 2*Hd;
                    *(float2*)&g_Ai[(long)row*Hd + h] = make_float2(v0, v1);
                }
            }
        }
    }
}

// ======== 3. k_post: cls/node heads + edge logits ===========================
// blocks: [0,528) heads; [528, 528+2048) edge groups of 8.
__global__ __launch_bounds__(128) void k_post(const float* __restrict__ clsoW,
                                              const float* __restrict__ clsob,
                                              const float* __restrict__ noW,
                                              const float* __restrict__ nob,
                                              const float* __restrict__ eoW,
                                              const float* __restrict__ eob,
                                              float* __restrict__ out) {
    __shared__ float red[16];
    __shared__ float2 sW[Hd];
    int blk = blockIdx.x;
    int tid = threadIdx.x;

    if (blk < 528) {
        const float *src, *oW, *ob;
        long obase;
        if (blk < 16) { src = g_cls_hidden + (long)blk*Hd; oW = clsoW; ob = clsob; obase = blk*2; }
        else { int r = blk - 16; src = g_node_hidden + (long)r*Hd; oW = noW; ob = nob; obase = 32 + r*2; }
        float a0 = 0.f, a1 = 0.f;
        #pragma unroll
        for (int u = 0; u < Hd/128; u++) {
            int h = tid + u*128;
            float t = src[h];
            a0 = fmaf(t, oW[2*h  ], a0);
            a1 = fmaf(t, oW[2*h+1], a1);
        }
        block_reduce2(a0, a1, red);
        if (tid == 0) { out[obase] = a0 + ob[0]; out[obase + 1] = a1 + ob[1]; }
        return;
    }

    int id = blk - 528;               // 0..2047
    int b  = id >> 7;
    int e0 = (id & 127) * 8;
    int m = g_n[b] + 1, mm = m*m;
    float c0 = g_invconst[0], c1 = g_invconst[1];
    long base0 = 32 + Bb*Kk*2 + ((long)b*Ee + e0)*2;

    if (e0 >= mm) {                   // all 8 invalid: constant fill, no eoW load
        if (tid < 16) out[base0 + tid] = (tid & 1) ? c1 : c0;
        return;
    }
    #pragma unroll
    for (int u = 0; u < Hd/128; u++) {
        int h = tid + u*128;
        sW[h] = ((const float2*)eoW)[h];
    }
    __syncthreads();
    for (int ee = 0; ee < 8; ee++) {
        int e = e0 + ee;
        long base = base0 + ee*2;
        if (e >= mm) {
            if (tid == 0) { out[base] = c0; out[base + 1] = c1; }
            continue;
        }
        int i = e / m, j = e - i*m;
        if (i > Kk-1) i = Kk-1;
        if (j > Kk-1) j = Kk-1;
        const float* aj = &g_Aj[(long)(b*Kk + j)*Hd];
        const float* ai = &g_Ai[(long)(b*Kk + i)*Hd];
        float a0 = 0.f, a1 = 0.f;
        #pragma unroll
        for (int u = 0; u < Hd/128; u++) {
            int h = tid + u*128;
            float t = tanh_fast(aj[h] + ai[h]);
            float2 w = sW[h];
            a0 = fmaf(t, w.x, a0);
            a1 = fmaf(t, w.y, a1);
        }
        block_reduce2(a0, a1, red);
        if (tid == 0) { out[base] = a0 + eob[0]; out[base + 1] = a1 + eob[1]; }
        __syncthreads();
    }
}

// ---------------------------------------------------------------------------
extern "C" void kernel_launch(void* const* d_in, const int* in_sizes, int n_in,
                              void* d_out, int out_size) {
    const float* seq   = (const float*)d_in[0];
    const int*   P     = (const int*)d_in[1];
    const float* nafW  = (const float*)d_in[2];
    const float* nafb  = (const float*)d_in[3];
    const float* clsW  = (const float*)d_in[4];
    const float* clsb  = (const float*)d_in[5];
    const float* clsoW = (const float*)d_in[6];
    const float* clsob = (const float*)d_in[7];
    const float* ndW   = (const float*)d_in[8];
    const float* ndb   = (const float*)d_in[9];
    const float* noW   = (const float*)d_in[10];
    const float* nob   = (const float*)d_in[11];
    const float* edW   = (const float*)d_in[12];
    const float* edb   = (const float*)d_in[13];
    const float* eoW   = (const float*)d_in[14];
    const float* eob   = (const float*)d_in[15];
    float* out = (float*)d_out;

    cudaFuncSetAttribute(k_gemm, cudaFuncAttributeMaxDynamicSharedMemorySize,
                         4*STAGE_B);

    k_prep<<<3617, 256>>>(seq, P, ndW, edW, edb, eoW, eob,
                          nafW, nafb, clsW, clsb);                       // idx 0
    k_gemm<<<dim3(NCAT/128, 512/64), 128, 4*STAGE_B>>>(ndb, edb);        // idx 1
    k_post<<<528 + 2048, 128>>>(clsoW, clsob, noW, nob, eoW, eob, out);  // idx 2
}

// round 10
// speedup vs baseline: 1.3208x; 1.3208x over previous
#include <cuda_runtime.h>
#include <cuda_fp16.h>
#include <cstdint>

#define Hd   1024
#define Bb   16
#define Ss   512
#define Kk   32
#define Ee   1024
#define NCAT 3072

// ---------------- scratch ----------------------------------------------------
__device__ __half g_Xh[512*Hd];          // full_nodes fp16 [512][1024] (row-major [m][k])
__device__ __half g_Wh[Hd*NCAT];         // Wcat fp16 [k][n] = [1024][3072]
__device__ __half g_W2h[Hd*2048];        // [nafW | clsW] fp16 [k][n] = [1024][2048]
__device__ __half g_X2h[Bb*Hd];          // cls tokens fp16 [16][1024]
__device__ float g_node_hidden[512*Hd];
__device__ float g_Aj[512*Hd];           // edge bias folded in
__device__ float g_Ai[512*Hd];
__device__ float g_cls_hidden[Bb*Hd];
__device__ float g_invconst[2];
__device__ int   g_n[Bb];

// ---------------- helpers ----------------------------------------------------
__device__ __forceinline__ float tanh_fast(float x) {
    float e = __expf(2.0f * x);
    return 1.0f - __fdividef(2.0f, e + 1.0f);
}

__device__ __forceinline__ uint32_t smem_u32(const void* p) {
    uint32_t a;
    asm("{ .reg .u64 t; cvta.to.shared.u64 t, %1; cvt.u32.u64 %0, t; }" : "=r"(a) : "l"(p));
    return a;
}

__device__ __forceinline__ void cp16(uint32_t saddr, const void* g) {
    asm volatile("cp.async.cg.shared.global [%0], [%1], 16;" :: "r"(saddr), "l"(g));
}
__device__ __forceinline__ void cp_commit() {
    asm volatile("cp.async.commit_group;");
}
template <int N>
__device__ __forceinline__ void cp_wait() {
    asm volatile("cp.async.wait_group %0;" :: "n"(N));
}

__device__ __forceinline__ void ldsm_x4(uint32_t& r0, uint32_t& r1, uint32_t& r2,
                                        uint32_t& r3, uint32_t addr) {
    asm volatile("ldmatrix.sync.aligned.m8n8.x4.shared.b16 {%0,%1,%2,%3}, [%4];"
                 : "=r"(r0), "=r"(r1), "=r"(r2), "=r"(r3) : "r"(addr));
}
__device__ __forceinline__ void ldsm_x2t(uint32_t& r0, uint32_t& r1, uint32_t addr) {
    asm volatile("ldmatrix.sync.aligned.m8n8.x2.trans.shared.b16 {%0,%1}, [%2];"
                 : "=r"(r0), "=r"(r1) : "r"(addr));
}
__device__ __forceinline__ void mma16816h(float* d, const uint32_t* a, const uint32_t* b) {
    asm volatile(
        "mma.sync.aligned.m16n8k16.row.col.f32.f16.f16.f32 "
        "{%0,%1,%2,%3}, {%4,%5,%6,%7}, {%8,%9}, {%0,%1,%2,%3};"
        : "+f"(d[0]), "+f"(d[1]), "+f"(d[2]), "+f"(d[3])
        : "r"(a[0]), "r"(a[1]), "r"(a[2]), "r"(a[3]), "r"(b[0]), "r"(b[1]));
}

__device__ __forceinline__ void block_reduce2(float& a0, float& a1, float* red) {
    #pragma unroll
    for (int o = 16; o > 0; o >>= 1) {
        a0 += __shfl_down_sync(0xffffffffu, a0, o);
        a1 += __shfl_down_sync(0xffffffffu, a1, o);
    }
    int w = threadIdx.x >> 5;
    if ((threadIdx.x & 31) == 0) { red[2*w] = a0; red[2*w+1] = a1; }
    __syncthreads();
    if (threadIdx.x == 0) {
        a0 = red[0]; a1 = red[1];
        for (int w2 = 1; w2 < (int)(blockDim.x >> 5); w2++) {
            a0 += red[2*w2]; a1 += red[2*w2+1];
        }
    }
}

// ======== 1. k_prep — ALL streaming, near-zero smem =========================
// blocks: [0,512) meta; [512,1536) Wcat rows; [1536,2560) W2 rows;
//         [2560,2576) cls-token convert; 2576 invconst.
__global__ __launch_bounds__(256) void k_prep(const float* __restrict__ seq,
                                              const int* __restrict__ P,
                                              const float* __restrict__ nodeW,
                                              const float* __restrict__ eW,
                                              const float* __restrict__ eb,
                                              const float* __restrict__ eoW,
                                              const float* __restrict__ eob,
                                              const float* __restrict__ nafW,
                                              const float* __restrict__ clsW) {
    __shared__ float red[16];
    int blk = blockIdx.x;
    int t   = threadIdx.x;

    if (blk < 512) {
        // ---- meta: segment mean (b,k); row k==n left for k_gemv2 ----
        int k = blk & 31, b = blk >> 5;
        int n = 0;
        #pragma unroll
        for (int j = 0; j < Kk - 1; j++) n += (P[b*Kk + 1 + j] > 0);
        if (k == 0 && t == 0) g_n[b] = n;
        long row = (long)(b*Kk + k) * Hd;
        if (k < n) {
            int end   = P[b*Kk + 1 + k];
            int start = (k == 0) ? 1 : (P[b*Kk + k] + 1);
            float inv = 1.0f / (float)(end - start + 1);
            #pragma unroll
            for (int u = 0; u < Hd/256; u++) {
                int h = t + u*256;
                float s = 0.0f;
                for (int p = start; p <= end; p++)
                    s += seq[((long)b*Ss + p)*Hd + h];
                g_Xh[row + h] = __float2half(s * inv);
            }
        } else if (k > n) {
            #pragma unroll
            for (int u = 0; u < Hd/256; u++)
                g_Xh[row + t + u*256] = __float2half(0.f);
        }
        return;
    }

    if (blk < 1536) {
        // ---- Wcat row k: [node | W0+W2 | W1-W2], fp16, [k][n] layout ----
        int k = blk - 512;
        const float* nw = nodeW + (long)k*Hd;
        const float* e0 = eW + (long)k*Hd;
        const float* e1 = eW + (long)(Hd + k)*Hd;
        const float* e2 = eW + (long)(2*Hd + k)*Hd;
        __half* dst = g_Wh + (long)k*NCAT;
        #pragma unroll
        for (int i = t*2; i < Hd; i += 512) {
            float2 a = *(const float2*)&nw[i];
            float2 b0 = *(const float2*)&e0[i];
            float2 b1 = *(const float2*)&e1[i];
            float2 b2 = *(const float2*)&e2[i];
            *(__half2*)&dst[i]        = __floats2half2_rn(a.x, a.y);
            *(__half2*)&dst[Hd + i]   = __floats2half2_rn(b0.x + b2.x, b0.y + b2.y);
            *(__half2*)&dst[2*Hd + i] = __floats2half2_rn(b1.x - b2.x, b1.y - b2.y);
        }
        return;
    }

    if (blk < 2560) {
        // ---- W2 row k: [nafW | clsW] fp16 [k][2048] ----
        int k = blk - 1536;
        const float* na = nafW + (long)k*Hd;
        const float* cl = clsW + (long)k*Hd;
        __half* dst = g_W2h + (long)k*2048;
        #pragma unroll
        for (int i = t*2; i < Hd; i += 512) {
            float2 a = *(const float2*)&na[i];
            float2 c = *(const float2*)&cl[i];
            *(__half2*)&dst[i]      = __floats2half2_rn(a.x, a.y);
            *(__half2*)&dst[Hd + i] = __floats2half2_rn(c.x, c.y);
        }
        return;
    }

    if (blk < 2576) {
        // ---- cls token -> fp16 ----
        int b = blk - 2560;
        #pragma unroll
        for (int i = t*2; i < Hd; i += 512) {
            float2 v = *(const float2*)&seq[(long)b*Ss*Hd + i];
            *(__half2*)&g_X2h[b*Hd + i] = __floats2half2_rn(v.x, v.y);
        }
        return;
    }

    // ---- invalid-edge constant ----
    {
        float a0 = 0.f, a1 = 0.f;
        #pragma unroll
        for (int u = 0; u < Hd/256; u++) {
            int h = t + u*256;
            float v = tanh_fast(eb[h]);
            a0 = fmaf(v, eoW[2*h  ], a0);
            a1 = fmaf(v, eoW[2*h+1], a1);
        }
        block_reduce2(a0, a1, red);
        if (t == 0) { g_invconst[0] = a0 + eob[0]; g_invconst[1] = a1 + eob[1]; }
    }
}

// ======== 2. k_gemv2: [naf|cls] = cls_tok(16x1024) @ W2(1024x2048) ==========
// 16 blocks of 128 cols, 128 thr (4 warps x 32 cols), 4-stage cp.async.
#define BROW 272
#define G2_A_OFF 0                 // 16 rows x 80B
#define G2_B_OFF 1280              // 32 rows x 272B
#define G2_STAGE (1280 + 32*BROW)  // 9984
__global__ __launch_bounds__(128) void k_gemv2(const float* __restrict__ nafb,
                                               const float* __restrict__ clsb) {
    extern __shared__ __align__(16) char sm2[];
    int tid = threadIdx.x, wid = tid >> 5, lane = tid & 31;
    const char* gA = (const char*)g_X2h;                         // row stride 2048B
    const char* gB = (const char*)g_W2h + blockIdx.x*256;        // row stride 4096B
    uint32_t smb = smem_u32(sm2);

    auto load_stage = [&](int ch, int st) {
        uint32_t sb = smb + st*G2_STAGE;
        if (tid < 64) {
            int r = tid >> 2, c = (tid & 3)*16;
            cp16(sb + G2_A_OFF + r*80 + c, gA + (long)r*2048 + ch*64 + c);
        }
        #pragma unroll
        for (int i = 0; i < 4; i++) {
            int j = tid + i*128;
            int r = j >> 4, c = (j & 15)*16;
            cp16(sb + G2_B_OFF + r*BROW + c, gB + (long)(ch*32 + r)*4096 + c);
        }
    };

    float acc[4][4];
    #pragma unroll
    for (int nt = 0; nt < 4; nt++)
        #pragma unroll
        for (int q = 0; q < 4; q++) acc[nt][q] = 0.0f;

    int brow = (lane & 7) + ((lane >> 3) & 1)*8;

    load_stage(0, 0); cp_commit();
    load_stage(1, 1); cp_commit();
    load_stage(2, 2); cp_commit();

    for (int ch = 0; ch < 32; ch++) {
        cp_wait<2>();
        __syncthreads();
        uint32_t sbase = smb + (ch & 3)*G2_STAGE;
        #pragma unroll
        for (int ks = 0; ks < 2; ks++) {
            uint32_t a[4];
            uint32_t ao = G2_A_OFF + (uint32_t)((lane & 15)*80 + ks*32 + (lane >> 4)*16);
            ldsm_x4(a[0], a[1], a[2], a[3], sbase + ao);
            #pragma unroll
            for (int nt = 0; nt < 4; nt++) {
                uint32_t bo = G2_B_OFF + (uint32_t)((ks*16 + brow)*BROW + wid*64 + nt*16);
                uint32_t b0, b1;
                ldsm_x2t(b0, b1, sbase + bo);
                uint32_t bf[2] = {b0, b1};
                mma16816h(acc[nt], a, bf);
            }
        }
        if (ch + 3 < 32) load_stage(ch + 3, (ch + 3) & 3);
        cp_commit();
    }

    int g = lane >> 2, t = lane & 3;
    bool is_cls = blockIdx.x >= 8;
    #pragma unroll
    for (int nt = 0; nt < 4; nt++) {
        int colg = blockIdx.x*128 + wid*32 + nt*8 + t*2;
        #pragma unroll
        for (int half = 0; half < 2; half++) {
            int b = g + half*8;                     // batch row
            float v0 = acc[nt][half*2 + 0];
            float v1 = acc[nt][half*2 + 1];
            if (!is_cls) {
                int col = colg;
                float n0 = v0 + nafb[col], n1 = v1 + nafb[col+1];
                int slot = g_n[b];
                *(__half2*)&g_Xh[(long)(b*Kk + slot)*Hd + col] = __floats2half2_rn(n0, n1);
            } else {
                int col = colg - 1024;
                g_cls_hidden[b*Hd + col]     = tanh_fast(v0 + clsb[col]);
                g_cls_hidden[b*Hd + col + 1] = tanh_fast(v1 + clsb[col+1]);
            }
        }
    }
}

// ======== 3. fp16 tensor GEMM, trans-B, 4-stage cp.async ====================
// C(512x3072) = X[m][k] @ Wcat[k][n]. Tile M=64, N=128, kchunk 32, grid (24,8).
#define A_OFF 0                    // 64 rows x 80B = 5120
#define B_OFF 5120                 // 32 rows x 272B = 8704
#define STAGE_B (5120 + 32*BROW)   // 13824
__global__ __launch_bounds__(128) void k_gemm(const float* __restrict__ node_b,
                                              const float* __restrict__ edge_b) {
    extern __shared__ __align__(16) char sm[];   // 4 * STAGE_B

    int tid  = threadIdx.x;
    int wid  = tid >> 5, lane = tid & 31;
    int wm   = wid & 1;
    int wn   = wid >> 1;
    int bn   = blockIdx.x, bm = blockIdx.y;

    const char* gX = (const char*)g_Xh + (long)bm*64*2048;       // row stride 2048B
    const char* gW = (const char*)g_Wh + bn*256;                 // row stride 6144B
    uint32_t smb = smem_u32(sm);

    auto load_stage = [&](int ch, int st) {
        uint32_t sb = smb + st*STAGE_B;
        #pragma unroll
        for (int i = 0; i < 6; i++) {
            int idx = tid + i*128;
            if (idx < 256) {
                int r = idx >> 2, c = (idx & 3)*16;
                cp16(sb + A_OFF + r*80 + c, gX + (long)r*2048 + ch*64 + c);
            } else {
                int j = idx - 256;
                int r = j >> 4, c = (j & 15)*16;
                cp16(sb + B_OFF + r*BROW + c, gW + (long)(ch*32 + r)*6144 + c);
            }
        }
    };

    float acc[2][8][4];
    #pragma unroll
    for (int mt = 0; mt < 2; mt++)
        #pragma unroll
        for (int nt = 0; nt < 8; nt++)
            #pragma unroll
            for (int q = 0; q < 4; q++) acc[mt][nt][q] = 0.0f;

    int a_row  = wm*32 + (lane & 15);
    int a_koff = (lane >> 4) * 16;
    int brow   = (lane & 7) + ((lane >> 3) & 1)*8;

    load_stage(0, 0); cp_commit();
    load_stage(1, 1); cp_commit();
    load_stage(2, 2); cp_commit();

    for (int ch = 0; ch < 32; ch++) {
        cp_wait<2>();
        __syncthreads();
        uint32_t sbase = smb + (ch & 3)*STAGE_B;

        #pragma unroll
        for (int ks = 0; ks < 2; ks++) {
            uint32_t a[2][4];
            #pragma unroll
            for (int mt = 0; mt < 2; mt++) {
                uint32_t ao = (uint32_t)((a_row + mt*16)*80 + ks*32 + a_koff);
                ldsm_x4(a[mt][0], a[mt][1], a[mt][2], a[mt][3], sbase + A_OFF + ao);
            }
            #pragma unroll
            for (int nt = 0; nt < 8; nt++) {
                uint32_t bo = (uint32_t)((ks*16 + brow)*BROW + (wn*64 + nt*8)*2);
                uint32_t b0, b1;
                ldsm_x2t(b0, b1, sbase + B_OFF + bo);
                uint32_t bf[2] = {b0, b1};
                #pragma unroll
                for (int mt = 0; mt < 2; mt++)
                    mma16816h(acc[mt][nt], a[mt], bf);
            }
        }
        if (ch + 3 < 32) load_stage(ch + 3, (ch + 3) & 3);
        cp_commit();
    }

    // ---- epilogue ----
    int g = lane >> 2, t = lane & 3;
    int region = bn >> 3;
    #pragma unroll
    for (int mt = 0; mt < 2; mt++) {
        #pragma unroll
        for (int nt = 0; nt < 8; nt++) {
            int col = bn*128 + wn*64 + nt*8 + t*2;
            #pragma unroll
            for (int half = 0; half < 2; half++) {
                int row = bm*64 + wm*32 + mt*16 + g + half*8;
                float v0 = acc[mt][nt][half*2 + 0];
                float v1 = acc[mt][nt][half*2 + 1];
                if (region == 0) {
                    float2 o = make_float2(tanh_fast(v0 + node_b[col]),
                                           tanh_fast(v1 + node_b[col+1]));
                    *(float2*)&g_node_hidden[(long)row*Hd + col] = o;
                } else if (region == 1) {
                    int h = col - Hd;
                    float2 o = make_float2(v0 + edge_b[h], v1 + edge_b[h+1]);
                    *(float2*)&g_Aj[(long)row*Hd + h] = o;
                } else {
                    int h = col - 2*Hd;
                    *(float2*)&g_Ai[(long)row*Hd + h] = make_float2(v0, v1);
                }
            }
        }
    }
}

// ======== 4. k_post: cls/node heads + edge logits ===========================
__global__ __launch_bounds__(128) void k_post(const float* __restrict__ clsoW,
                                              const float* __restrict__ clsob,
                                              const float* __restrict__ noW,
                                              const float* __restrict__ nob,
                                              const float* __restrict__ eoW,
                                              const float* __restrict__ eob,
                                              float* __restrict__ out) {
    __shared__ float red[16];
    __shared__ float2 sW[Hd];
    int blk = blockIdx.x;
    int tid = threadIdx.x;

    if (blk < 528) {
        const float *src, *oW, *ob;
        long obase;
        if (blk < 16) { src = g_cls_hidden + (long)blk*Hd; oW = clsoW; ob = clsob; obase = blk*2; }
        else { int r = blk - 16; src = g_node_hidden + (long)r*Hd; oW = noW; ob = nob; obase = 32 + r*2; }
        float a0 = 0.f, a1 = 0.f;
        #pragma unroll
        for (int u = 0; u < Hd/128; u++) {
            int h = tid + u*128;
            float t = src[h];
            a0 = fmaf(t, oW[2*h  ], a0);
            a1 = fmaf(t, oW[2*h+1], a1);
        }
        block_reduce2(a0, a1, red);
        if (tid == 0) { out[obase] = a0 + ob[0]; out[obase + 1] = a1 + ob[1]; }
        return;
    }

    int id = blk - 528;               // 0..2047
    int b  = id >> 7;
    int e0 = (id & 127) * 8;
    int m = g_n[b] + 1, mm = m*m;
    float c0 = g_invconst[0], c1 = g_invconst[1];
    long base0 = 32 + Bb*Kk*2 + ((long)b*Ee + e0)*2;

    if (e0 >= mm) {                   // all 8 invalid: constant fill
        if (tid < 16) out[base0 + tid] = (tid & 1) ? c1 : c0;
        return;
    }
    #pragma unroll
    for (int u = 0; u < Hd/128; u++) {
        int h = tid + u*128;
        sW[h] = ((const float2*)eoW)[h];
    }
    __syncthreads();
    for (int ee = 0; ee < 8; ee++) {
        int e = e0 + ee;
        long base = base0 + ee*2;
        if (e >= mm) {
            if (tid == 0) { out[base] = c0; out[base + 1] = c1; }
            continue;
        }
        int i = e / m, j = e - i*m;
        if (i > Kk-1) i = Kk-1;
        if (j > Kk-1) j = Kk-1;
        const float* aj = &g_Aj[(long)(b*Kk + j)*Hd];
        const float* ai = &g_Ai[(long)(b*Kk + i)*Hd];
        float a0 = 0.f, a1 = 0.f;
        #pragma unroll
        for (int u = 0; u < Hd/128; u++) {
            int h = tid + u*128;
            float t = tanh_fast(aj[h] + ai[h]);
            float2 w = sW[h];
            a0 = fmaf(t, w.x, a0);
            a1 = fmaf(t, w.y, a1);
        }
        block_reduce2(a0, a1, red);
        if (tid == 0) { out[base] = a0 + eob[0]; out[base + 1] = a1 + eob[1]; }
        __syncthreads();
    }
}

// ---------------------------------------------------------------------------
extern "C" void kernel_launch(void* const* d_in, const int* in_sizes, int n_in,
                              void* d_out, int out_size) {
    const float* seq   = (const float*)d_in[0];
    const int*   P     = (const int*)d_in[1];
    const float* nafW  = (const float*)d_in[2];
    const float* nafb  = (const float*)d_in[3];
    const float* clsW  = (const float*)d_in[4];
    const float* clsb  = (const float*)d_in[5];
    const float* clsoW = (const float*)d_in[6];
    const float* clsob = (const float*)d_in[7];
    const float* ndW   = (const float*)d_in[8];
    const float* ndb   = (const float*)d_in[9];
    const float* noW   = (const float*)d_in[10];
    const float* nob   = (const float*)d_in[11];
    const float* edW   = (const float*)d_in[12];
    const float* edb   = (const float*)d_in[13];
    const float* eoW   = (const float*)d_in[14];
    const float* eob   = (const float*)d_in[15];
    float* out = (float*)d_out;

    cudaFuncSetAttribute(k_gemm,  cudaFuncAttributeMaxDynamicSharedMemorySize, 4*STAGE_B);
    cudaFuncSetAttribute(k_gemv2, cudaFuncAttributeMaxDynamicSharedMemorySize, 4*G2_STAGE);

    k_prep<<<2577, 256>>>(seq, P, ndW, edW, edb, eoW, eob, nafW, clsW);     // idx 0
    k_gemv2<<<16, 128, 4*G2_STAGE>>>(nafb, clsb);                           // idx 1
    k_gemm<<<dim3(NCAT/128, 512/64), 128, 4*STAGE_B>>>(ndb, edb);           // idx 2
    k_post<<<528 + 2048, 128>>>(clsoW, clsob, noW, nob, eoW, eob, out);     // idx 3
}

// round 11
// speedup vs baseline: 1.4214x; 1.0762x over previous
#include <cuda_runtime.h>
#include <cuda_fp16.h>
#include <cstdint>

#define Hd   1024
#define Bb   16
#define Ss   512
#define Kk   32
#define Ee   1024
#define NCAT 3072

// ---------------- scratch ----------------------------------------------------
__device__ __half g_Xh[512*Hd];          // full_nodes fp16 [512][1024] (row-major [m][k])
__device__ __half g_Wh[Hd*NCAT];         // Wcat fp16 [k][n] = [1024][3072]
__device__ __half g_W2h[Hd*2048];        // [nafW | clsW] fp16 [k][n] = [1024][2048]
__device__ __half g_X2h[Bb*Hd];          // cls tokens fp16 [16][1024]
__device__ float g_node_hidden[512*Hd];
__device__ float g_Aj[512*Hd];           // edge bias folded in
__device__ float g_Ai[512*Hd];
__device__ float g_cls_hidden[Bb*Hd];
__device__ float g_invconst[2];
__device__ int   g_n[Bb];

// ---------------- helpers ----------------------------------------------------
__device__ __forceinline__ float tanh_fast(float x) {
    float e = __expf(2.0f * x);
    return 1.0f - __fdividef(2.0f, e + 1.0f);
}

__device__ __forceinline__ uint32_t smem_u32(const void* p) {
    uint32_t a;
    asm("{ .reg .u64 t; cvta.to.shared.u64 t, %1; cvt.u32.u64 %0, t; }" : "=r"(a) : "l"(p));
    return a;
}

__device__ __forceinline__ void cp16(uint32_t saddr, const void* g) {
    asm volatile("cp.async.cg.shared.global [%0], [%1], 16;" :: "r"(saddr), "l"(g));
}
__device__ __forceinline__ void cp_commit() {
    asm volatile("cp.async.commit_group;");
}
template <int N>
__device__ __forceinline__ void cp_wait() {
    asm volatile("cp.async.wait_group %0;" :: "n"(N));
}

__device__ __forceinline__ void ldsm_x4(uint32_t& r0, uint32_t& r1, uint32_t& r2,
                                        uint32_t& r3, uint32_t addr) {
    asm volatile("ldmatrix.sync.aligned.m8n8.x4.shared.b16 {%0,%1,%2,%3}, [%4];"
                 : "=r"(r0), "=r"(r1), "=r"(r2), "=r"(r3) : "r"(addr));
}
__device__ __forceinline__ void ldsm_x2t(uint32_t& r0, uint32_t& r1, uint32_t addr) {
    asm volatile("ldmatrix.sync.aligned.m8n8.x2.trans.shared.b16 {%0,%1}, [%2];"
                 : "=r"(r0), "=r"(r1) : "r"(addr));
}
__device__ __forceinline__ void mma16816h(float* d, const uint32_t* a, const uint32_t* b) {
    asm volatile(
        "mma.sync.aligned.m16n8k16.row.col.f32.f16.f16.f32 "
        "{%0,%1,%2,%3}, {%4,%5,%6,%7}, {%8,%9}, {%0,%1,%2,%3};"
        : "+f"(d[0]), "+f"(d[1]), "+f"(d[2]), "+f"(d[3])
        : "r"(a[0]), "r"(a[1]), "r"(a[2]), "r"(a[3]), "r"(b[0]), "r"(b[1]));
}

__device__ __forceinline__ void block_reduce2(float& a0, float& a1, float* red) {
    #pragma unroll
    for (int o = 16; o > 0; o >>= 1) {
        a0 += __shfl_down_sync(0xffffffffu, a0, o);
        a1 += __shfl_down_sync(0xffffffffu, a1, o);
    }
    int w = threadIdx.x >> 5;
    if ((threadIdx.x & 31) == 0) { red[2*w] = a0; red[2*w+1] = a1; }
    __syncthreads();
    if (threadIdx.x == 0) {
        a0 = red[0]; a1 = red[1];
        for (int w2 = 1; w2 < (int)(blockDim.x >> 5); w2++) {
            a0 += red[2*w2]; a1 += red[2*w2+1];
        }
    }
}

__device__ __forceinline__ void warp_reduce2(float& a0, float& a1) {
    #pragma unroll
    for (int o = 16; o > 0; o >>= 1) {
        a0 += __shfl_down_sync(0xffffffffu, a0, o);
        a1 += __shfl_down_sync(0xffffffffu, a1, o);
    }
}

// ======== 1. k_prep — ALL streaming, near-zero smem =========================
// blocks: [0,512) meta; [512,1536) Wcat rows; [1536,2560) W2 rows;
//         [2560,2576) cls-token convert; 2576 invconst.
__global__ __launch_bounds__(256) void k_prep(const float* __restrict__ seq,
                                              const int* __restrict__ P,
                                              const float* __restrict__ nodeW,
                                              const float* __restrict__ eW,
                                              const float* __restrict__ eb,
                                              const float* __restrict__ eoW,
                                              const float* __restrict__ eob,
                                              const float* __restrict__ nafW,
                                              const float* __restrict__ clsW) {
    __shared__ float red[16];
    int blk = blockIdx.x;
    int t   = threadIdx.x;

    if (blk < 512) {
        // ---- meta: segment mean (b,k); row k==n left for k_gemv2 ----
        int k = blk & 31, b = blk >> 5;
        int n = 0;
        #pragma unroll
        for (int j = 0; j < Kk - 1; j++) n += (P[b*Kk + 1 + j] > 0);
        if (k == 0 && t == 0) g_n[b] = n;
        long row = (long)(b*Kk + k) * Hd;
        if (k < n) {
            int end   = P[b*Kk + 1 + k];
            int start = (k == 0) ? 1 : (P[b*Kk + k] + 1);
            float inv = 1.0f / (float)(end - start + 1);
            #pragma unroll
            for (int u = 0; u < Hd/256; u++) {
                int h = t + u*256;
                float s = 0.0f;
                for (int p = start; p <= end; p++)
                    s += seq[((long)b*Ss + p)*Hd + h];
                g_Xh[row + h] = __float2half(s * inv);
            }
        } else if (k > n) {
            #pragma unroll
            for (int u = 0; u < Hd/256; u++)
                g_Xh[row + t + u*256] = __float2half(0.f);
        }
        return;
    }

    if (blk < 1536) {
        // ---- Wcat row k: [node | W0+W2 | W1-W2], fp16, [k][n] layout ----
        int k = blk - 512;
        const float* nw = nodeW + (long)k*Hd;
        const float* e0 = eW + (long)k*Hd;
        const float* e1 = eW + (long)(Hd + k)*Hd;
        const float* e2 = eW + (long)(2*Hd + k)*Hd;
        __half* dst = g_Wh + (long)k*NCAT;
        #pragma unroll
        for (int i = t*2; i < Hd; i += 512) {
            float2 a = *(const float2*)&nw[i];
            float2 b0 = *(const float2*)&e0[i];
            float2 b1 = *(const float2*)&e1[i];
            float2 b2 = *(const float2*)&e2[i];
            *(__half2*)&dst[i]        = __floats2half2_rn(a.x, a.y);
            *(__half2*)&dst[Hd + i]   = __floats2half2_rn(b0.x + b2.x, b0.y + b2.y);
            *(__half2*)&dst[2*Hd + i] = __floats2half2_rn(b1.x - b2.x, b1.y - b2.y);
        }
        return;
    }

    if (blk < 2560) {
        // ---- W2 row k: [nafW | clsW] fp16 [k][2048] ----
        int k = blk - 1536;
        const float* na = nafW + (long)k*Hd;
        const float* cl = clsW + (long)k*Hd;
        __half* dst = g_W2h + (long)k*2048;
        #pragma unroll
        for (int i = t*2; i < Hd; i += 512) {
            float2 a = *(const float2*)&na[i];
            float2 c = *(const float2*)&cl[i];
            *(__half2*)&dst[i]      = __floats2half2_rn(a.x, a.y);
            *(__half2*)&dst[Hd + i] = __floats2half2_rn(c.x, c.y);
        }
        return;
    }

    if (blk < 2576) {
        // ---- cls token -> fp16 ----
        int b = blk - 2560;
        #pragma unroll
        for (int i = t*2; i < Hd; i += 512) {
            float2 v = *(const float2*)&seq[(long)b*Ss*Hd + i];
            *(__half2*)&g_X2h[b*Hd + i] = __floats2half2_rn(v.x, v.y);
        }
        return;
    }

    // ---- invalid-edge constant ----
    {
        float a0 = 0.f, a1 = 0.f;
        #pragma unroll
        for (int u = 0; u < Hd/256; u++) {
            int h = t + u*256;
            float v = tanh_fast(eb[h]);
            a0 = fmaf(v, eoW[2*h  ], a0);
            a1 = fmaf(v, eoW[2*h+1], a1);
        }
        block_reduce2(a0, a1, red);
        if (t == 0) { g_invconst[0] = a0 + eob[0]; g_invconst[1] = a1 + eob[1]; }
    }
}

// ======== 2. k_gemv2: [naf|cls] = cls_tok(16x1024) @ W2(1024x2048) ==========
// 16 blocks of 128 cols, 128 thr (4 warps x 32 cols), 4-stage cp.async.
#define BROW 272
#define G2_A_OFF 0                 // 16 rows x 80B
#define G2_B_OFF 1280              // 32 rows x 272B
#define G2_STAGE (1280 + 32*BROW)  // 9984
__global__ __launch_bounds__(128) void k_gemv2(const float* __restrict__ nafb,
                                               const float* __restrict__ clsb) {
    extern __shared__ __align__(16) char sm2[];
    int tid = threadIdx.x, wid = tid >> 5, lane = tid & 31;
    const char* gA = (const char*)g_X2h;                         // row stride 2048B
    const char* gB = (const char*)g_W2h + blockIdx.x*256;        // row stride 4096B
    uint32_t smb = smem_u32(sm2);

    auto load_stage = [&](int ch, int st) {
        uint32_t sb = smb + st*G2_STAGE;
        if (tid < 64) {
            int r = tid >> 2, c = (tid & 3)*16;
            cp16(sb + G2_A_OFF + r*80 + c, gA + (long)r*2048 + ch*64 + c);
        }
        #pragma unroll
        for (int i = 0; i < 4; i++) {
            int j = tid + i*128;
            int r = j >> 4, c = (j & 15)*16;
            cp16(sb + G2_B_OFF + r*BROW + c, gB + (long)(ch*32 + r)*4096 + c);
        }
    };

    float acc[4][4];
    #pragma unroll
    for (int nt = 0; nt < 4; nt++)
        #pragma unroll
        for (int q = 0; q < 4; q++) acc[nt][q] = 0.0f;

    int brow = (lane & 7) + ((lane >> 3) & 1)*8;

    load_stage(0, 0); cp_commit();
    load_stage(1, 1); cp_commit();
    load_stage(2, 2); cp_commit();

    for (int ch = 0; ch < 32; ch++) {
        cp_wait<2>();
        __syncthreads();
        uint32_t sbase = smb + (ch & 3)*G2_STAGE;
        #pragma unroll
        for (int ks = 0; ks < 2; ks++) {
            uint32_t a[4];
            uint32_t ao = G2_A_OFF + (uint32_t)((lane & 15)*80 + ks*32 + (lane >> 4)*16);
            ldsm_x4(a[0], a[1], a[2], a[3], sbase + ao);
            #pragma unroll
            for (int nt = 0; nt < 4; nt++) {
                uint32_t bo = G2_B_OFF + (uint32_t)((ks*16 + brow)*BROW + wid*64 + nt*16);
                uint32_t b0, b1;
                ldsm_x2t(b0, b1, sbase + bo);
                uint32_t bf[2] = {b0, b1};
                mma16816h(acc[nt], a, bf);
            }
        }
        if (ch + 3 < 32) load_stage(ch + 3, (ch + 3) & 3);
        cp_commit();
    }

    int g = lane >> 2, t = lane & 3;
    bool is_cls = blockIdx.x >= 8;
    #pragma unroll
    for (int nt = 0; nt < 4; nt++) {
        int colg = blockIdx.x*128 + wid*32 + nt*8 + t*2;
        #pragma unroll
        for (int half = 0; half < 2; half++) {
            int b = g + half*8;                     // batch row
            float v0 = acc[nt][half*2 + 0];
            float v1 = acc[nt][half*2 + 1];
            if (!is_cls) {
                int col = colg;
                float n0 = v0 + nafb[col], n1 = v1 + nafb[col+1];
                int slot = g_n[b];
                *(__half2*)&g_Xh[(long)(b*Kk + slot)*Hd + col] = __floats2half2_rn(n0, n1);
            } else {
                int col = colg - 1024;
                g_cls_hidden[b*Hd + col]     = tanh_fast(v0 + clsb[col]);
                g_cls_hidden[b*Hd + col + 1] = tanh_fast(v1 + clsb[col+1]);
            }
        }
    }
}

// ======== 3. fp16 tensor GEMM, trans-B, 4-stage cp.async ====================
// C(512x3072) = X[m][k] @ Wcat[k][n]. Tile M=64, N=128, kchunk 32, grid (24,8).
#define A_OFF 0                    // 64 rows x 80B = 5120
#define B_OFF 5120                 // 32 rows x 272B = 8704
#define STAGE_B (5120 + 32*BROW)   // 13824
__global__ __launch_bounds__(128) void k_gemm(const float* __restrict__ node_b,
                                              const float* __restrict__ edge_b) {
    extern __shared__ __align__(16) char sm[];   // 4 * STAGE_B

    int tid  = threadIdx.x;
    int wid  = tid >> 5, lane = tid & 31;
    int wm   = wid & 1;
    int wn   = wid >> 1;
    int bn   = blockIdx.x, bm = blockIdx.y;

    const char* gX = (const char*)g_Xh + (long)bm*64*2048;       // row stride 2048B
    const char* gW = (const char*)g_Wh + bn*256;                 // row stride 6144B
    uint32_t smb = smem_u32(sm);

    auto load_stage = [&](int ch, int st) {
        uint32_t sb = smb + st*STAGE_B;
        #pragma unroll
        for (int i = 0; i < 6; i++) {
            int idx = tid + i*128;
            if (idx < 256) {
                int r = idx >> 2, c = (idx & 3)*16;
                cp16(sb + A_OFF + r*80 + c, gX + (long)r*2048 + ch*64 + c);
            } else {
                int j = idx - 256;
                int r = j >> 4, c = (j & 15)*16;
                cp16(sb + B_OFF + r*BROW + c, gW + (long)(ch*32 + r)*6144 + c);
            }
        }
    };

    float acc[2][8][4];
    #pragma unroll
    for (int mt = 0; mt < 2; mt++)
        #pragma unroll
        for (int nt = 0; nt < 8; nt++)
            #pragma unroll
            for (int q = 0; q < 4; q++) acc[mt][nt][q] = 0.0f;

    int a_row  = wm*32 + (lane & 15);
    int a_koff = (lane >> 4) * 16;
    int brow   = (lane & 7) + ((lane >> 3) & 1)*8;

    load_stage(0, 0); cp_commit();
    load_stage(1, 1); cp_commit();
    load_stage(2, 2); cp_commit();

    for (int ch = 0; ch < 32; ch++) {
        cp_wait<2>();
        __syncthreads();
        uint32_t sbase = smb + (ch & 3)*STAGE_B;

        #pragma unroll
        for (int ks = 0; ks < 2; ks++) {
            uint32_t a[2][4];
            #pragma unroll
            for (int mt = 0; mt < 2; mt++) {
                uint32_t ao = (uint32_t)((a_row + mt*16)*80 + ks*32 + a_koff);
                ldsm_x4(a[mt][0], a[mt][1], a[mt][2], a[mt][3], sbase + A_OFF + ao);
            }
            #pragma unroll
            for (int nt = 0; nt < 8; nt++) {
                uint32_t bo = (uint32_t)((ks*16 + brow)*BROW + (wn*64 + nt*8)*2);
                uint32_t b0, b1;
                ldsm_x2t(b0, b1, sbase + B_OFF + bo);
                uint32_t bf[2] = {b0, b1};
                #pragma unroll
                for (int mt = 0; mt < 2; mt++)
                    mma16816h(acc[mt][nt], a[mt], bf);
            }
        }
        if (ch + 3 < 32) load_stage(ch + 3, (ch + 3) & 3);
        cp_commit();
    }

    // ---- epilogue ----
    int g = lane >> 2, t = lane & 3;
    int region = bn >> 3;
    #pragma unroll
    for (int mt = 0; mt < 2; mt++) {
        #pragma unroll
        for (int nt = 0; nt < 8; nt++) {
            int col = bn*128 + wn*64 + nt*8 + t*2;
            #pragma unroll
            for (int half = 0; half < 2; half++) {
                int row = bm*64 + wm*32 + mt*16 + g + half*8;
                float v0 = acc[mt][nt][half*2 + 0];
                float v1 = acc[mt][nt][half*2 + 1];
                if (region == 0) {
                    float2 o = make_float2(tanh_fast(v0 + node_b[col]),
                                           tanh_fast(v1 + node_b[col+1]));
                    *(float2*)&g_node_hidden[(long)row*Hd + col] = o;
                } else if (region == 1) {
                    int h = col - Hd;
                    float2 o = make_float2(v0 + edge_b[h], v1 + edge_b[h+1]);
                    *(float2*)&g_Aj[(long)row*Hd + h] = o;
                } else {
                    int h = col - 2*Hd;
                    *(float2*)&g_Ai[(long)row*Hd + h] = make_float2(v0, v1);
                }
            }
        }
    }
}

// ======== 4. k_post: warp-per-row heads + warp-per-edge logits ==============
// blocks: [0,66) heads (8 warp-rows each, 528 total);
//         [66, 66+2048) edge groups (8 warps = 8 edges each).
__global__ __launch_bounds__(256) void k_post(const float* __restrict__ clsoW,
                                              const float* __restrict__ clsob,
                                              const float* __restrict__ noW,
                                              const float* __restrict__ nob,
                                              const float* __restrict__ eoW,
                                              const float* __restrict__ eob,
                                              float* __restrict__ out) {
    __shared__ float2 sW[Hd];
    int blk = blockIdx.x;
    int tid = threadIdx.x;
    int wid = tid >> 5, lane = tid & 31;

    if (blk < 66) {
        int r = blk*8 + wid;           // 0..527
        const float *src, *oW, *ob;
        long obase;
        if (r < 16) { src = g_cls_hidden + (long)r*Hd; oW = clsoW; ob = clsob; obase = r*2; }
        else { int rr = r - 16; src = g_node_hidden + (long)rr*Hd; oW = noW; ob = nob; obase = 32 + rr*2; }
        float a0 = 0.f, a1 = 0.f;
        #pragma unroll
        for (int s = 0; s < 8; s++) {
            int h = s*128 + lane*4;
            float4 v  = *(const float4*)&src[h];
            float4 wa = *(const float4*)&oW[2*h];      // (w[h].x, w[h].y, w[h+1].x, w[h+1].y)
            float4 wb = *(const float4*)&oW[2*h + 4];
            a0 = fmaf(v.x, wa.x, a0); a1 = fmaf(v.x, wa.y, a1);
            a0 = fmaf(v.y, wa.z, a0); a1 = fmaf(v.y, wa.w, a1);
            a0 = fmaf(v.z, wb.x, a0); a1 = fmaf(v.z, wb.y, a1);
            a0 = fmaf(v.w, wb.z, a0); a1 = fmaf(v.w, wb.w, a1);
        }
        warp_reduce2(a0, a1);
        if (lane == 0) { out[obase] = a0 + ob[0]; out[obase + 1] = a1 + ob[1]; }
        return;
    }

    int id = blk - 66;                 // 0..2047
    int b  = id >> 7;
    int e0 = (id & 127) * 8;
    int m = g_n[b] + 1, mm = m*m;
    float c0 = g_invconst[0], c1 = g_invconst[1];
    long base0 = 32 + Bb*Kk*2 + ((long)b*Ee + e0)*2;

    if (e0 >= mm) {                    // all 8 invalid: constant fill, no eoW load
        if (tid < 16) out[base0 + tid] = (tid & 1) ? c1 : c0;
        return;
    }
    #pragma unroll
    for (int u = 0; u < 4; u++) {
        int h = tid + u*256;
        sW[h] = ((const float2*)eoW)[h];
    }
    __syncthreads();

    int e = e0 + wid;                  // this warp's edge
    long base = base0 + wid*2;
    if (e >= mm) {
        if (lane == 0) { out[base] = c0; out[base + 1] = c1; }
        return;
    }
    int i = e / m, j = e - i*m;
    if (i > Kk-1) i = Kk-1;
    if (j > Kk-1) j = Kk-1;
    const float4* aj = (const float4*)&g_Aj[(long)(b*Kk + j)*Hd];
    const float4* ai = (const float4*)&g_Ai[(long)(b*Kk + i)*Hd];
    float a0 = 0.f, a1 = 0.f;
    #pragma unroll
    for (int s = 0; s < 8; s++) {
        int q = s*32 + lane;           // float4 index; coalesced across lanes
        float4 x = aj[q];
        float4 y = ai[q];
        int h = q*4;
        float t0 = tanh_fast(x.x + y.x);
        float t1 = tanh_fast(x.y + y.y);
        float t2 = tanh_fast(x.z + y.z);
        float t3 = tanh_fast(x.w + y.w);
        float2 w0 = sW[h], w1 = sW[h+1], w2 = sW[h+2], w3 = sW[h+3];
        a0 = fmaf(t0, w0.x, a0); a1 = fmaf(t0, w0.y, a1);
        a0 = fmaf(t1, w1.x, a0); a1 = fmaf(t1, w1.y, a1);
        a0 = fmaf(t2, w2.x, a0); a1 = fmaf(t2, w2.y, a1);
        a0 = fmaf(t3, w3.x, a0); a1 = fmaf(t3, w3.y, a1);
    }
    warp_reduce2(a0, a1);
    if (lane == 0) { out[base] = a0 + eob[0]; out[base + 1] = a1 + eob[1]; }
}

// ---------------------------------------------------------------------------
extern "C" void kernel_launch(void* const* d_in, const int* in_sizes, int n_in,
                              void* d_out, int out_size) {
    const float* seq   = (const float*)d_in[0];
    const int*   P     = (const int*)d_in[1];
    const float* nafW  = (const float*)d_in[2];
    const float* nafb  = (const float*)d_in[3];
    const float* clsW  = (const float*)d_in[4];
    const float* clsb  = (const float*)d_in[5];
    const float* clsoW = (const float*)d_in[6];
    const float* clsob = (const float*)d_in[7];
    const float* ndW   = (const float*)d_in[8];
    const float* ndb   = (const float*)d_in[9];
    const float* noW   = (const float*)d_in[10];
    const float* nob   = (const float*)d_in[11];
    const float* edW   = (const float*)d_in[12];
    const float* edb   = (const float*)d_in[13];
    const float* eoW   = (const float*)d_in[14];
    const float* eob   = (const float*)d_in[15];
    float* out = (float*)d_out;

    cudaFuncSetAttribute(k_gemm,  cudaFuncAttributeMaxDynamicSharedMemorySize, 4*STAGE_B);
    cudaFuncSetAttribute(k_gemv2, cudaFuncAttributeMaxDynamicSharedMemorySize, 4*G2_STAGE);

    k_prep<<<2577, 256>>>(seq, P, ndW, edW, edb, eoW, eob, nafW, clsW);     // idx 0
    k_gemv2<<<16, 128, 4*G2_STAGE>>>(nafb, clsb);                           // idx 1
    k_gemm<<<dim3(NCAT/128, 512/64), 128, 4*STAGE_B>>>(ndb, edb);           // idx 2
    k_post<<<66 + 2048, 256>>>(clsoW, clsob, noW, nob, eoW, eob, out);      // idx 3
}